// round 2
// baseline (speedup 1.0000x reference)
#include <cuda_runtime.h>
#include <math.h>

#define THRESH 0.1f

// ---------------- scratch (no allocations allowed) ----------------
__device__ float g_bufA[52428800];   // 1600*8*64*64  (200 MiB) — conv outputs (syn)
__device__ float g_bufB[13107200];   // 1600*8*32*32  ( 50 MiB) — pooled spikes
__device__ float g_w0[8 * 9 * 2];    // [co][k][ci] layout
__device__ float g_w1[16 * 9 * 8];
__device__ float g_w2[32 * 9 * 16];
__device__ float g_w3[64 * 9 * 32];
__device__ float g_wl[11 * 1024];

// ---------------- weight norm for conv, exact op-order emulation ----------------
// norm = sqrt( sum_i round(v_i*v_i) ) sequential; w = round(round(g*v)/norm)
// output repacked OIHW -> [co][ky*3+kx][ci]  (ci innermost = HWIO chain order)
template <int CIN, int COUT>
__global__ void wnorm_conv(const float* __restrict__ v, const float* __restrict__ g,
                           float* __restrict__ w) {
    int co = blockIdx.x * blockDim.x + threadIdx.x;
    if (co >= COUT) return;
    const float* vr = v + (size_t)co * CIN * 9;
    float s = 0.f;
    for (int i = 0; i < CIN * 9; i++) {
        float t = vr[i];
        s = __fadd_rn(s, __fmul_rn(t, t));
    }
    float norm = sqrtf(s);
    float gg = g[co];
    for (int ci = 0; ci < CIN; ci++) {
        for (int k = 0; k < 9; k++) {
            float val = __fdiv_rn(__fmul_rn(gg, vr[ci * 9 + k]), norm);
            w[((size_t)co * 9 + k) * CIN + ci] = val;
        }
    }
}

__global__ void wnorm_lin(const float* __restrict__ v, const float* __restrict__ g,
                          float* __restrict__ w) {
    int r = threadIdx.x;
    if (r >= 11) return;
    const float* vr = v + (size_t)r * 1024;
    float s = 0.f;
    for (int i = 0; i < 1024; i++) {
        float t = vr[i];
        s = __fadd_rn(s, __fmul_rn(t, t));
    }
    float norm = sqrtf(s);
    float gg = g[r];
    for (int i = 0; i < 1024; i++)
        w[(size_t)r * 1024 + i] = __fdiv_rn(__fmul_rn(gg, vr[i]), norm);
}

// ---------------- 3x3 SAME conv, one block per image ----------------
// Sequential FMA chain per output in (ky, kx, ci) order, ci innermost.
// Weights staged in smem in [co][k][ci] layout.
template <int CIN, int COUT, int H>
__global__ void conv3x3_same(const float* __restrict__ in, const float* __restrict__ wt,
                             float* __restrict__ out) {
    const int W = H, HW = H * W;
    extern __shared__ float smem[];
    float* sin = smem;                 // CIN*HW
    float* sw = smem + CIN * HW;       // COUT*9*CIN

    int n = blockIdx.x;
    const float* inp = in + (size_t)n * CIN * HW;
    for (int i = threadIdx.x; i < CIN * HW; i += blockDim.x) sin[i] = inp[i];
    for (int i = threadIdx.x; i < COUT * 9 * CIN; i += blockDim.x) sw[i] = wt[i];
    __syncthreads();

    float* outp = out + (size_t)n * COUT * HW;
    for (int idx = threadIdx.x; idx < COUT * HW; idx += blockDim.x) {
        int co = idx / HW;
        int p = idx - co * HW;
        int y = p / W;
        int x = p - y * W;
        const float* wbase = sw + (size_t)co * 9 * CIN;
        float acc = 0.f;
#pragma unroll
        for (int ky = 0; ky < 3; ky++) {
            int yy = y + ky - 1;
            if (yy < 0 || yy >= H) continue;   // padding zeros: fma(0,w,acc)==acc, skipping is exact
#pragma unroll
            for (int kx = 0; kx < 3; kx++) {
                int xx = x + kx - 1;
                if (xx < 0 || xx >= W) continue;
                const float* ip = sin + yy * W + xx;
                const float* wp = wbase + (ky * 3 + kx) * CIN;
                for (int ci = 0; ci < CIN; ci++) {
                    acc = __fmaf_rn(ip[ci * HW], wp[ci], acc);
                }
            }
        }
        outp[idx] = acc;
    }
}

// ---------------- fused IAF (integrate-and-fire over T) + 2x2 avg pool ----------------
template <int C, int H, int T>
__global__ void iaf_pool_kernel(const float* __restrict__ syn, float* __restrict__ out, int B) {
    const int W = H, HW = H * W, H2 = H / 2, W2 = W / 2, HW2 = H2 * W2;
    int idx = blockIdx.x * blockDim.x + threadIdx.x;
    int total = B * C * HW2;
    if (idx >= total) return;
    int x2 = idx % W2;
    int r = idx / W2;
    int y2 = r % H2;
    r /= H2;
    int c = r % C;
    int b = r / C;

    const size_t stride = (size_t)C * HW;
    const size_t ostride = (size_t)C * HW2;
    const float* p = syn + ((size_t)b * T) * stride + (size_t)c * HW + (size_t)(2 * y2) * W + 2 * x2;
    float* q = out + ((size_t)b * T) * ostride + (size_t)c * HW2 + (size_t)y2 * W2 + x2;

    float v0 = 0.f, v1 = 0.f, v2 = 0.f, v3 = 0.f;
#pragma unroll 2
    for (int t = 0; t < T; t++) {
        v0 = __fadd_rn(v0, p[0]);
        v1 = __fadd_rn(v1, p[1]);
        v2 = __fadd_rn(v2, p[W]);
        v3 = __fadd_rn(v3, p[W + 1]);
        float s = 0.f;
        if (v0 >= THRESH) { v0 = __fadd_rn(v0, -THRESH); s += 0.25f; }
        if (v1 >= THRESH) { v1 = __fadd_rn(v1, -THRESH); s += 0.25f; }
        if (v2 >= THRESH) { v2 = __fadd_rn(v2, -THRESH); s += 0.25f; }
        if (v3 >= THRESH) { v3 = __fadd_rn(v3, -THRESH); s += 0.25f; }
        *q = s;
        p += stride;
        q += ostride;
    }
}

// ---------------- final linear: (BT,1024) @ (11,1024)^T ----------------
// One sequential FMA chain per (n, class).
__global__ void linear_kernel(const float* __restrict__ in, const float* __restrict__ w,
                              float* __restrict__ out) {
    int n = blockIdx.x;
    __shared__ float srow[1024];
    for (int i = threadIdx.x; i < 1024; i += blockDim.x) srow[i] = in[(size_t)n * 1024 + i];
    __syncthreads();
    int cls = threadIdx.x;
    if (cls >= 11) return;
    const float* wr = w + (size_t)cls * 1024;
    float acc = 0.f;
    for (int i = 0; i < 1024; i++) acc = __fmaf_rn(srow[i], wr[i], acc);
    out[(size_t)n * 11 + cls] = acc;
}

extern "C" void kernel_launch(void* const* d_in, const int* in_sizes, int n_in,
                              void* d_out, int out_size) {
    const float* x   = (const float*)d_in[0];
    const float* c0v = (const float*)d_in[1];
    const float* c0g = (const float*)d_in[2];
    const float* c1v = (const float*)d_in[3];
    const float* c1g = (const float*)d_in[4];
    const float* c2v = (const float*)d_in[5];
    const float* c2g = (const float*)d_in[6];
    const float* c3v = (const float*)d_in[7];
    const float* c3g = (const float*)d_in[8];
    const float* lv  = (const float*)d_in[9];
    const float* lg  = (const float*)d_in[10];

    float *bufA, *bufB, *w0, *w1, *w2, *w3, *wl;
    cudaGetSymbolAddress((void**)&bufA, g_bufA);
    cudaGetSymbolAddress((void**)&bufB, g_bufB);
    cudaGetSymbolAddress((void**)&w0, g_w0);
    cudaGetSymbolAddress((void**)&w1, g_w1);
    cudaGetSymbolAddress((void**)&w2, g_w2);
    cudaGetSymbolAddress((void**)&w3, g_w3);
    cudaGetSymbolAddress((void**)&wl, g_wl);

    const int B = 32, T = 50, BT = B * T;

    // weight norms (exact op-order emulation)
    wnorm_conv<2, 8><<<1, 8>>>(c0v, c0g, w0);
    wnorm_conv<8, 16><<<1, 16>>>(c1v, c1g, w1);
    wnorm_conv<16, 32><<<1, 32>>>(c2v, c2g, w2);
    wnorm_conv<32, 64><<<1, 64>>>(c3v, c3g, w3);
    wnorm_lin<<<1, 32>>>(lv, lg, wl);

    // shared mem sizes (input image + all weights)
    const int smem0 = (2 * 64 * 64 + 8 * 2 * 9) * 4;
    const int smem1 = (8 * 32 * 32 + 16 * 8 * 9) * 4;
    const int smem2 = (16 * 16 * 16 + 32 * 16 * 9) * 4;
    const int smem3 = (32 * 8 * 8 + 64 * 32 * 9) * 4;   // 81920 -> opt-in

    cudaFuncSetAttribute(conv3x3_same<32, 64, 8>,
                         cudaFuncAttributeMaxDynamicSharedMemorySize, smem3);

    // layer 0: conv(2->8, 64x64) -> IAF+pool -> 32x32 spikes
    conv3x3_same<2, 8, 64><<<BT, 256, smem0>>>(x, w0, bufA);
    {
        int total = B * 8 * 32 * 32;
        iaf_pool_kernel<8, 64, 50><<<(total + 255) / 256, 256>>>(bufA, bufB, B);
    }
    // layer 1: conv(8->16, 32x32) -> IAF+pool -> 16x16
    conv3x3_same<8, 16, 32><<<BT, 256, smem1>>>(bufB, w1, bufA);
    {
        int total = B * 16 * 16 * 16;
        iaf_pool_kernel<16, 32, 50><<<(total + 255) / 256, 256>>>(bufA, bufB, B);
    }
    // layer 2: conv(16->32, 16x16) -> IAF+pool -> 8x8
    conv3x3_same<16, 32, 16><<<BT, 256, smem2>>>(bufB, w2, bufA);
    {
        int total = B * 32 * 8 * 8;
        iaf_pool_kernel<32, 16, 50><<<(total + 255) / 256, 256>>>(bufA, bufB, B);
    }
    // layer 3: conv(32->64, 8x8) -> IAF+pool -> 4x4
    conv3x3_same<32, 64, 8><<<BT, 256, smem3>>>(bufB, w3, bufA);
    {
        int total = B * 64 * 4 * 4;
        iaf_pool_kernel<64, 8, 50><<<(total + 255) / 256, 256>>>(bufA, bufB, B);
    }
    // linear
    linear_kernel<<<BT, 32>>>(bufB, wl, (float*)d_out);
}

// round 3
// speedup vs baseline: 2.2214x; 2.2214x over previous
#include <cuda_runtime.h>
#include <math.h>

#define THRESH 0.1f

// ---------------- scratch (no allocations allowed) ----------------
__device__ float g_bufA[52428800];   // 1600*8*64*64  (200 MiB) — conv outputs (syn)
__device__ float g_bufB[13107200];   // 1600*8*32*32  ( 50 MiB) — pooled spikes
__device__ float g_w0[9 * 2 * 8];    // [k][ci][co] layout
__device__ float g_w1[9 * 8 * 16];
__device__ float g_w2[9 * 16 * 32];
__device__ float g_w3[9 * 32 * 64];
__device__ float g_wl[11 * 1024];

// ---------------- fused weight norm (all layers, one launch) ----------------
// Per-row: s = sum_i round(v_i*v_i) sequential; norm = sqrtf(s);
// w = round(round(g*v)/norm). Conv weights repacked OIHW -> [k][ci][co].
__global__ void wnorm_all(const float* __restrict__ c0v, const float* __restrict__ c0g,
                          const float* __restrict__ c1v, const float* __restrict__ c1g,
                          const float* __restrict__ c2v, const float* __restrict__ c2g,
                          const float* __restrict__ c3v, const float* __restrict__ c3g,
                          const float* __restrict__ lv,  const float* __restrict__ lg,
                          float* __restrict__ w0, float* __restrict__ w1,
                          float* __restrict__ w2, float* __restrict__ w3,
                          float* __restrict__ wl) {
    int r = blockIdx.x;
    const float* v = 0; const float* g = 0; float* w = 0;
    int CIN = 0, COUT = 0, co = 0;
    bool lin = false;
    if (r < 8)        { v = c0v; g = c0g; w = w0; CIN = 2;  COUT = 8;  co = r; }
    else if (r < 24)  { v = c1v; g = c1g; w = w1; CIN = 8;  COUT = 16; co = r - 8; }
    else if (r < 56)  { v = c2v; g = c2g; w = w2; CIN = 16; COUT = 32; co = r - 24; }
    else if (r < 120) { v = c3v; g = c3g; w = w3; CIN = 32; COUT = 64; co = r - 56; }
    else              { lin = true; co = r - 120; }

    __shared__ float snorm;
    if (!lin) {
        const float* vr = v + (size_t)co * CIN * 9;
        if (threadIdx.x == 0) {
            float s = 0.f;
            for (int i = 0; i < CIN * 9; i++) s = __fadd_rn(s, __fmul_rn(vr[i], vr[i]));
            snorm = sqrtf(s);
        }
        __syncthreads();
        float norm = snorm, gg = g[co];
        for (int idx = threadIdx.x; idx < CIN * 9; idx += blockDim.x) {
            int ci = idx / 9, k = idx % 9;
            w[((size_t)k * CIN + ci) * COUT + co] = __fdiv_rn(__fmul_rn(gg, vr[idx]), norm);
        }
    } else {
        const float* vr = lv + (size_t)co * 1024;
        if (threadIdx.x == 0) {
            float s = 0.f;
            for (int i = 0; i < 1024; i++) s = __fadd_rn(s, __fmul_rn(vr[i], vr[i]));
            snorm = sqrtf(s);
        }
        __syncthreads();
        float norm = snorm, gg = lg[co];
        for (int i = threadIdx.x; i < 1024; i += blockDim.x)
            wl[(size_t)co * 1024 + i] = __fdiv_rn(__fmul_rn(gg, vr[i]), norm);
    }
}

// ---------------- 3x3 SAME conv, register-blocked 2x2 x 8-channel ----------------
// Zero-padded smem input tile (branch-free). FMA chain per output in exact
// (ky, kx, ci) order, ci innermost — bit-identical to the reference emulation.
// Weights in smem in [k][ci][co] layout -> float4 broadcast loads.
template <int CIN, int COUT, int H, int IPB>
__global__ void conv3x3_blk(const float* __restrict__ in, const float* __restrict__ wt,
                            float* __restrict__ out) {
    const int W = H, HW = H * W, PW = W + 2, PHW = (H + 2) * PW;
    const int HW4 = HW / 4, W2 = W / 2, NCG = COUT / 8;
    extern __shared__ float smem[];
    float* sin = smem;                         // IPB*CIN*PHW (zero padded)
    float* sw = smem + IPB * CIN * PHW;        // 9*CIN*COUT

    const int n0 = blockIdx.x * IPB;
    for (int i = threadIdx.x; i < IPB * CIN * PHW; i += blockDim.x) sin[i] = 0.f;
    for (int i = threadIdx.x; i < 9 * CIN * COUT; i += blockDim.x) sw[i] = wt[i];
    __syncthreads();
    for (int i = threadIdx.x; i < IPB * CIN * HW; i += blockDim.x) {
        int img = i / (CIN * HW);
        int rem = i - img * (CIN * HW);
        int ci = rem / HW;
        int p = rem - ci * HW;
        int y = p / W;
        int x = p - y * W;
        sin[img * CIN * PHW + ci * PHW + (y + 1) * PW + (x + 1)] = in[(size_t)n0 * CIN * HW + i];
    }
    __syncthreads();

    const int ITEMS = IPB * HW4 * NCG;
    for (int item = threadIdx.x; item < ITEMS; item += blockDim.x) {
        int cg = item / (IPB * HW4);
        int rem = item - cg * (IPB * HW4);
        int img = rem / HW4;
        int q = rem - img * HW4;
        int y2 = q / W2, x2 = q - y2 * W2;
        int y0 = 2 * y2, x0 = 2 * x2;
        const float* simg = sin + img * CIN * PHW;

        float acc[8][4];
#pragma unroll
        for (int c = 0; c < 8; c++) {
            acc[c][0] = 0.f; acc[c][1] = 0.f; acc[c][2] = 0.f; acc[c][3] = 0.f;
        }
#pragma unroll
        for (int ky = 0; ky < 3; ky++) {
#pragma unroll
            for (int kx = 0; kx < 3; kx++) {
                const float* ip = simg + (y0 + ky) * PW + (x0 + kx);
                const float* wp = sw + (ky * 3 + kx) * CIN * COUT + cg * 8;
#pragma unroll 4
                for (int ci = 0; ci < CIN; ci++) {
                    float i00 = ip[ci * PHW];
                    float i01 = ip[ci * PHW + 1];
                    float i10 = ip[ci * PHW + PW];
                    float i11 = ip[ci * PHW + PW + 1];
                    const float4 wa = *reinterpret_cast<const float4*>(wp + ci * COUT);
                    const float4 wb = *reinterpret_cast<const float4*>(wp + ci * COUT + 4);
                    float wv[8] = {wa.x, wa.y, wa.z, wa.w, wb.x, wb.y, wb.z, wb.w};
#pragma unroll
                    for (int c = 0; c < 8; c++) {
                        acc[c][0] = __fmaf_rn(i00, wv[c], acc[c][0]);
                        acc[c][1] = __fmaf_rn(i01, wv[c], acc[c][1]);
                        acc[c][2] = __fmaf_rn(i10, wv[c], acc[c][2]);
                        acc[c][3] = __fmaf_rn(i11, wv[c], acc[c][3]);
                    }
                }
            }
        }
        float* op = out + ((size_t)(n0 + img) * COUT + cg * 8) * HW + y0 * W + x0;
#pragma unroll
        for (int c = 0; c < 8; c++) {
            float2 r0; r0.x = acc[c][0]; r0.y = acc[c][1];
            float2 r1; r1.x = acc[c][2]; r1.y = acc[c][3];
            *reinterpret_cast<float2*>(op + c * HW) = r0;
            *reinterpret_cast<float2*>(op + c * HW + W) = r1;
        }
    }
}

// ---------------- fused IAF (integrate-and-fire over T) + 2x2 avg pool ----------------
template <int C, int H, int T>
__global__ void iaf_pool_kernel(const float* __restrict__ syn, float* __restrict__ out, int B) {
    const int W = H, HW = H * W, H2 = H / 2, W2 = W / 2, HW2 = H2 * W2;
    int idx = blockIdx.x * blockDim.x + threadIdx.x;
    int total = B * C * HW2;
    if (idx >= total) return;
    int x2 = idx % W2;
    int r = idx / W2;
    int y2 = r % H2;
    r /= H2;
    int c = r % C;
    int b = r / C;

    const size_t stride = (size_t)C * HW;
    const size_t ostride = (size_t)C * HW2;
    const float* p = syn + ((size_t)b * T) * stride + (size_t)c * HW + (size_t)(2 * y2) * W + 2 * x2;
    float* q = out + ((size_t)b * T) * ostride + (size_t)c * HW2 + (size_t)y2 * W2 + x2;

    float v0 = 0.f, v1 = 0.f, v2 = 0.f, v3 = 0.f;
#pragma unroll 2
    for (int t = 0; t < T; t++) {
        const float2 a = *reinterpret_cast<const float2*>(p);
        const float2 bb = *reinterpret_cast<const float2*>(p + W);
        v0 = __fadd_rn(v0, a.x);
        v1 = __fadd_rn(v1, a.y);
        v2 = __fadd_rn(v2, bb.x);
        v3 = __fadd_rn(v3, bb.y);
        float s = 0.f;
        if (v0 >= THRESH) { v0 = __fadd_rn(v0, -THRESH); s += 0.25f; }
        if (v1 >= THRESH) { v1 = __fadd_rn(v1, -THRESH); s += 0.25f; }
        if (v2 >= THRESH) { v2 = __fadd_rn(v2, -THRESH); s += 0.25f; }
        if (v3 >= THRESH) { v3 = __fadd_rn(v3, -THRESH); s += 0.25f; }
        *q = s;
        p += stride;
        q += ostride;
    }
}

// ---------------- final linear: (BT,1024) @ (11,1024)^T ----------------
__global__ void linear_kernel(const float* __restrict__ in, const float* __restrict__ w,
                              float* __restrict__ out) {
    int n = blockIdx.x;
    __shared__ float srow[1024];
    for (int i = threadIdx.x; i < 1024; i += blockDim.x) srow[i] = in[(size_t)n * 1024 + i];
    __syncthreads();
    int cls = threadIdx.x;
    if (cls >= 11) return;
    const float* wr = w + (size_t)cls * 1024;
    float acc = 0.f;
    for (int i = 0; i < 1024; i++) acc = __fmaf_rn(srow[i], wr[i], acc);
    out[(size_t)n * 11 + cls] = acc;
}

extern "C" void kernel_launch(void* const* d_in, const int* in_sizes, int n_in,
                              void* d_out, int out_size) {
    const float* x   = (const float*)d_in[0];
    const float* c0v = (const float*)d_in[1];
    const float* c0g = (const float*)d_in[2];
    const float* c1v = (const float*)d_in[3];
    const float* c1g = (const float*)d_in[4];
    const float* c2v = (const float*)d_in[5];
    const float* c2g = (const float*)d_in[6];
    const float* c3v = (const float*)d_in[7];
    const float* c3g = (const float*)d_in[8];
    const float* lv  = (const float*)d_in[9];
    const float* lg  = (const float*)d_in[10];

    float *bufA, *bufB, *w0, *w1, *w2, *w3, *wl;
    cudaGetSymbolAddress((void**)&bufA, g_bufA);
    cudaGetSymbolAddress((void**)&bufB, g_bufB);
    cudaGetSymbolAddress((void**)&w0, g_w0);
    cudaGetSymbolAddress((void**)&w1, g_w1);
    cudaGetSymbolAddress((void**)&w2, g_w2);
    cudaGetSymbolAddress((void**)&w3, g_w3);
    cudaGetSymbolAddress((void**)&wl, g_wl);

    const int B = 32, T = 50, BT = B * T;

    // all weight norms in one launch
    wnorm_all<<<131, 64>>>(c0v, c0g, c1v, c1g, c2v, c2g, c3v, c3g, lv, lg,
                           w0, w1, w2, w3, wl);

    // smem: padded inputs + weights
    const int smem0 = (1 * 2 * 66 * 66 + 9 * 2 * 8) * 4;       // 35424
    const int smem1 = (1 * 8 * 34 * 34 + 9 * 8 * 16) * 4;      // 41600
    const int smem2 = (2 * 16 * 18 * 18 + 9 * 16 * 32) * 4;    // 59904
    const int smem3 = (4 * 32 * 10 * 10 + 9 * 32 * 64) * 4;    // 124928

    cudaFuncSetAttribute(conv3x3_blk<2, 8, 64, 1>,
                         cudaFuncAttributeMaxDynamicSharedMemorySize, smem0);
    cudaFuncSetAttribute(conv3x3_blk<8, 16, 32, 1>,
                         cudaFuncAttributeMaxDynamicSharedMemorySize, smem1);
    cudaFuncSetAttribute(conv3x3_blk<16, 32, 16, 2>,
                         cudaFuncAttributeMaxDynamicSharedMemorySize, smem2);
    cudaFuncSetAttribute(conv3x3_blk<32, 64, 8, 4>,
                         cudaFuncAttributeMaxDynamicSharedMemorySize, smem3);

    // layer 0: conv(2->8, 64x64) -> IAF+pool -> 32x32 spikes
    conv3x3_blk<2, 8, 64, 1><<<BT, 256, smem0>>>(x, w0, bufA);
    {
        int total = B * 8 * 32 * 32;
        iaf_pool_kernel<8, 64, 50><<<(total + 255) / 256, 256>>>(bufA, bufB, B);
    }
    // layer 1: conv(8->16, 32x32) -> IAF+pool -> 16x16
    conv3x3_blk<8, 16, 32, 1><<<BT, 256, smem1>>>(bufB, w1, bufA);
    {
        int total = B * 16 * 16 * 16;
        iaf_pool_kernel<16, 32, 50><<<(total + 255) / 256, 256>>>(bufA, bufB, B);
    }
    // layer 2: conv(16->32, 16x16) -> IAF+pool -> 8x8
    conv3x3_blk<16, 32, 16, 2><<<BT / 2, 256, smem2>>>(bufB, w2, bufA);
    {
        int total = B * 32 * 8 * 8;
        iaf_pool_kernel<32, 16, 50><<<(total + 255) / 256, 256>>>(bufA, bufB, B);
    }
    // layer 3: conv(32->64, 8x8) -> IAF+pool -> 4x4
    conv3x3_blk<32, 64, 8, 4><<<BT / 4, 256, smem3>>>(bufB, w3, bufA);
    {
        int total = B * 64 * 4 * 4;
        iaf_pool_kernel<64, 8, 50><<<(total + 255) / 256, 256>>>(bufA, bufB, B);
    }
    // linear
    linear_kernel<<<BT, 32>>>(bufB, wl, (float*)d_out);
}

// round 5
// speedup vs baseline: 2.2559x; 1.0156x over previous
#include <cuda_runtime.h>
#include <math.h>

#define THRESH 0.1f

// ---------------- scratch (no allocations allowed) ----------------
__device__ float g_bufA[26214400];   // max: 1600*16*32*32 (100 MiB) — conv outputs (syn)
__device__ float g_bufB[13107200];   // max: 1600*8*32*32  ( 50 MiB) — pooled spikes
__device__ float g_w0[9 * 2 * 8];    // [k][ci][co] layout
__device__ float g_w1[9 * 8 * 16];
__device__ float g_w2[9 * 16 * 32];
__device__ float g_w3[9 * 32 * 64];
__device__ float g_wl[11 * 1024];

// ---------------- fused weight norm (all layers, one launch) ----------------
__global__ void wnorm_all(const float* __restrict__ c0v, const float* __restrict__ c0g,
                          const float* __restrict__ c1v, const float* __restrict__ c1g,
                          const float* __restrict__ c2v, const float* __restrict__ c2g,
                          const float* __restrict__ c3v, const float* __restrict__ c3g,
                          const float* __restrict__ lv,  const float* __restrict__ lg,
                          float* __restrict__ w0, float* __restrict__ w1,
                          float* __restrict__ w2, float* __restrict__ w3,
                          float* __restrict__ wl) {
    int r = blockIdx.x;
    const float* v = 0; const float* g = 0; float* w = 0;
    int CIN = 0, COUT = 0, co = 0;
    bool lin = false;
    if (r < 8)        { v = c0v; g = c0g; w = w0; CIN = 2;  COUT = 8;  co = r; }
    else if (r < 24)  { v = c1v; g = c1g; w = w1; CIN = 8;  COUT = 16; co = r - 8; }
    else if (r < 56)  { v = c2v; g = c2g; w = w2; CIN = 16; COUT = 32; co = r - 24; }
    else if (r < 120) { v = c3v; g = c3g; w = w3; CIN = 32; COUT = 64; co = r - 56; }
    else              { lin = true; co = r - 120; }

    __shared__ float snorm;
    if (!lin) {
        const float* vr = v + (size_t)co * CIN * 9;
        if (threadIdx.x == 0) {
            float s = 0.f;
            for (int i = 0; i < CIN * 9; i++) s = __fadd_rn(s, __fmul_rn(vr[i], vr[i]));
            snorm = sqrtf(s);
        }
        __syncthreads();
        float norm = snorm, gg = g[co];
        for (int idx = threadIdx.x; idx < CIN * 9; idx += blockDim.x) {
            int ci = idx / 9, k = idx % 9;
            w[((size_t)k * CIN + ci) * COUT + co] = __fdiv_rn(__fmul_rn(gg, vr[idx]), norm);
        }
    } else {
        const float* vr = lv + (size_t)co * 1024;
        if (threadIdx.x == 0) {
            float s = 0.f;
            for (int i = 0; i < 1024; i++) s = __fadd_rn(s, __fmul_rn(vr[i], vr[i]));
            snorm = sqrtf(s);
        }
        __syncthreads();
        float norm = snorm, gg = lg[co];
        for (int i = threadIdx.x; i < 1024; i += blockDim.x)
            wl[(size_t)co * 1024 + i] = __fdiv_rn(__fmul_rn(gg, vr[i]), norm);
    }
}

// ---------------- layer 0 fully fused: conv(2->8,64x64) + IAF(T=50) + 2x2 pool ----------------
// Block = (image b, 16x32 pre-pool spatial tile). 128 threads = 8x16 pooled pixels.
// Thread holds 8 couts x 4 membranes in registers across all T; syn never hits HBM.
__global__ void __launch_bounds__(128) l0_fused(const float* __restrict__ x,
                                                const float* __restrict__ wt,
                                                float* __restrict__ out) {
    const int PW = 36, CPH = 18 * 36;       // padded tile: 2 x 18 x 36 (cols 0..33 used)
    __shared__ float sw[144];               // [k][ci][co] = 9*2*8
    __shared__ float sin[2 * 18 * 36];

    const int b = blockIdx.x >> 3;
    const int tile = blockIdx.x & 7;
    const int ty0 = (tile >> 1) * 16;       // pre-pool row origin (0,16,32,48)
    const int tx0 = (tile & 1) * 32;        // pre-pool col origin (0,32)
    const int tid = threadIdx.x;
    for (int i = tid; i < 144; i += 128) sw[i] = wt[i];   // FIXED: full 144 weights

    const int py = tid >> 4, px = tid & 15; // pooled pixel within tile
    const int y0 = 2 * py, x0 = 2 * px;     // quad origin in padded-local coords

    float m[8][4];
#pragma unroll
    for (int c = 0; c < 8; c++) { m[c][0] = 0.f; m[c][1] = 0.f; m[c][2] = 0.f; m[c][3] = 0.f; }

    const int Y2 = (ty0 >> 1) + py, X2 = (tx0 >> 1) + px;

    for (int t = 0; t < 50; t++) {
        const float* xp = x + ((size_t)(b * 50 + t)) * 2 * 4096;
        // cooperative padded tile load (zero outside image)
        for (int i = tid; i < 2 * 18 * 34; i += 128) {
            int c = i / 612;
            int r = i - c * 612;
            int yy = r / 34, xx = r - (r / 34) * 34;
            int gy = ty0 + yy - 1, gx = tx0 + xx - 1;
            float v = 0.f;
            if (gy >= 0 && gy < 64 && gx >= 0 && gx < 64) v = xp[c * 4096 + gy * 64 + gx];
            sin[c * CPH + yy * PW + xx] = v;
        }
        __syncthreads();

        // preload 2ci x 4x4 input window into regs (aligned float2 loads)
        float inr[2][4][4];
#pragma unroll
        for (int ci = 0; ci < 2; ci++) {
#pragma unroll
            for (int r = 0; r < 4; r++) {
                const float* rp = sin + ci * CPH + (y0 + r) * PW + x0;
                float2 a = *reinterpret_cast<const float2*>(rp);
                float2 bb = *reinterpret_cast<const float2*>(rp + 2);
                inr[ci][r][0] = a.x; inr[ci][r][1] = a.y;
                inr[ci][r][2] = bb.x; inr[ci][r][3] = bb.y;
            }
        }
        __syncthreads();   // sin free for next t

        float acc[8][4];
#pragma unroll
        for (int c = 0; c < 8; c++) { acc[c][0] = 0.f; acc[c][1] = 0.f; acc[c][2] = 0.f; acc[c][3] = 0.f; }
#pragma unroll
        for (int ky = 0; ky < 3; ky++) {
#pragma unroll
            for (int kx = 0; kx < 3; kx++) {
#pragma unroll
                for (int ci = 0; ci < 2; ci++) {
                    float i00 = inr[ci][ky][kx];
                    float i01 = inr[ci][ky][kx + 1];
                    float i10 = inr[ci][ky + 1][kx];
                    float i11 = inr[ci][ky + 1][kx + 1];
                    const float* wp = sw + ((ky * 3 + kx) * 2 + ci) * 8;
                    const float4 wa = *reinterpret_cast<const float4*>(wp);
                    const float4 wb = *reinterpret_cast<const float4*>(wp + 4);
                    float wv[8] = {wa.x, wa.y, wa.z, wa.w, wb.x, wb.y, wb.z, wb.w};
#pragma unroll
                    for (int c = 0; c < 8; c++) {
                        acc[c][0] = __fmaf_rn(i00, wv[c], acc[c][0]);
                        acc[c][1] = __fmaf_rn(i01, wv[c], acc[c][1]);
                        acc[c][2] = __fmaf_rn(i10, wv[c], acc[c][2]);
                        acc[c][3] = __fmaf_rn(i11, wv[c], acc[c][3]);
                    }
                }
            }
        }

        // IAF membrane update + pool + store
        float* op = out + ((size_t)(b * 50 + t) * 8) * 1024 + Y2 * 32 + X2;
#pragma unroll
        for (int c = 0; c < 8; c++) {
            float s = 0.f;
            m[c][0] = __fadd_rn(m[c][0], acc[c][0]);
            m[c][1] = __fadd_rn(m[c][1], acc[c][1]);
            m[c][2] = __fadd_rn(m[c][2], acc[c][2]);
            m[c][3] = __fadd_rn(m[c][3], acc[c][3]);
            if (m[c][0] >= THRESH) { m[c][0] = __fadd_rn(m[c][0], -THRESH); s += 0.25f; }
            if (m[c][1] >= THRESH) { m[c][1] = __fadd_rn(m[c][1], -THRESH); s += 0.25f; }
            if (m[c][2] >= THRESH) { m[c][2] = __fadd_rn(m[c][2], -THRESH); s += 0.25f; }
            if (m[c][3] >= THRESH) { m[c][3] = __fadd_rn(m[c][3], -THRESH); s += 0.25f; }
            op[c * 1024] = s;
        }
    }
}

// ---------------- 3x3 SAME conv, register-blocked 2x2 x 8-channel ----------------
// Zero-padded smem tile; FMA chain per output exactly (ky,kx,ci), ci innermost.
// Input loads are float2 where compile-time aligned (kx=0,2).
template <int CIN, int COUT, int H, int IPB>
__global__ void conv3x3_blk(const float* __restrict__ in, const float* __restrict__ wt,
                            float* __restrict__ out) {
    const int W = H, HW = H * W, PW = W + 2, PHW = (H + 2) * PW;
    const int HW4 = HW / 4, W2 = W / 2, NCG = COUT / 8;
    extern __shared__ float smem[];
    float* sin = smem;                         // IPB*CIN*PHW (zero padded)
    float* sw = smem + IPB * CIN * PHW;        // 9*CIN*COUT

    const int n0 = blockIdx.x * IPB;
    for (int i = threadIdx.x; i < IPB * CIN * PHW; i += blockDim.x) sin[i] = 0.f;
    for (int i = threadIdx.x; i < 9 * CIN * COUT; i += blockDim.x) sw[i] = wt[i];
    __syncthreads();
    for (int i = threadIdx.x; i < IPB * CIN * HW; i += blockDim.x) {
        int img = i / (CIN * HW);
        int rem = i - img * (CIN * HW);
        int ci = rem / HW;
        int p = rem - ci * HW;
        int y = p / W;
        int x = p - y * W;
        sin[img * CIN * PHW + ci * PHW + (y + 1) * PW + (x + 1)] = in[(size_t)n0 * CIN * HW + i];
    }
    __syncthreads();

    const int ITEMS = IPB * HW4 * NCG;
    for (int item = threadIdx.x; item < ITEMS; item += blockDim.x) {
        int cg = item / (IPB * HW4);
        int rem = item - cg * (IPB * HW4);
        int img = rem / HW4;
        int q = rem - img * HW4;
        int y2 = q / W2, x2 = q - y2 * W2;
        int y0 = 2 * y2, x0 = 2 * x2;
        const float* simg = sin + img * CIN * PHW;

        float acc[8][4];
#pragma unroll
        for (int c = 0; c < 8; c++) {
            acc[c][0] = 0.f; acc[c][1] = 0.f; acc[c][2] = 0.f; acc[c][3] = 0.f;
        }
#pragma unroll
        for (int ky = 0; ky < 3; ky++) {
#pragma unroll
            for (int kx = 0; kx < 3; kx++) {
                const float* ip = simg + (y0 + ky) * PW + (x0 + kx);
                const float* wp = sw + (ky * 3 + kx) * CIN * COUT + cg * 8;
#pragma unroll 4
                for (int ci = 0; ci < CIN; ci++) {
                    float i00, i01, i10, i11;
                    if (kx != 1) {   // compile-time: even offset -> aligned float2
                        float2 a = *reinterpret_cast<const float2*>(ip + ci * PHW);
                        float2 bb = *reinterpret_cast<const float2*>(ip + ci * PHW + PW);
                        i00 = a.x; i01 = a.y; i10 = bb.x; i11 = bb.y;
                    } else {
                        i00 = ip[ci * PHW];
                        i01 = ip[ci * PHW + 1];
                        i10 = ip[ci * PHW + PW];
                        i11 = ip[ci * PHW + PW + 1];
                    }
                    const float4 wa = *reinterpret_cast<const float4*>(wp + ci * COUT);
                    const float4 wb = *reinterpret_cast<const float4*>(wp + ci * COUT + 4);
                    float wv[8] = {wa.x, wa.y, wa.z, wa.w, wb.x, wb.y, wb.z, wb.w};
#pragma unroll
                    for (int c = 0; c < 8; c++) {
                        acc[c][0] = __fmaf_rn(i00, wv[c], acc[c][0]);
                        acc[c][1] = __fmaf_rn(i01, wv[c], acc[c][1]);
                        acc[c][2] = __fmaf_rn(i10, wv[c], acc[c][2]);
                        acc[c][3] = __fmaf_rn(i11, wv[c], acc[c][3]);
                    }
                }
            }
        }
        float* op = out + ((size_t)(n0 + img) * COUT + cg * 8) * HW + y0 * W + x0;
#pragma unroll
        for (int c = 0; c < 8; c++) {
            float2 r0; r0.x = acc[c][0]; r0.y = acc[c][1];
            float2 r1; r1.x = acc[c][2]; r1.y = acc[c][3];
            *reinterpret_cast<float2*>(op + c * HW) = r0;
            *reinterpret_cast<float2*>(op + c * HW + W) = r1;
        }
    }
}

// ---------------- fused IAF (integrate-and-fire over T) + 2x2 avg pool ----------------
template <int C, int H, int T>
__global__ void iaf_pool_kernel(const float* __restrict__ syn, float* __restrict__ out, int B) {
    const int W = H, HW = H * W, H2 = H / 2, W2 = W / 2, HW2 = H2 * W2;
    int idx = blockIdx.x * blockDim.x + threadIdx.x;
    int total = B * C * HW2;
    if (idx >= total) return;
    int x2 = idx % W2;
    int r = idx / W2;
    int y2 = r % H2;
    r /= H2;
    int c = r % C;
    int b = r / C;

    const size_t stride = (size_t)C * HW;
    const size_t ostride = (size_t)C * HW2;
    const float* p = syn + ((size_t)b * T) * stride + (size_t)c * HW + (size_t)(2 * y2) * W + 2 * x2;
    float* q = out + ((size_t)b * T) * ostride + (size_t)c * HW2 + (size_t)y2 * W2 + x2;

    float v0 = 0.f, v1 = 0.f, v2 = 0.f, v3 = 0.f;
#pragma unroll 2
    for (int t = 0; t < T; t++) {
        const float2 a = *reinterpret_cast<const float2*>(p);
        const float2 bb = *reinterpret_cast<const float2*>(p + W);
        v0 = __fadd_rn(v0, a.x);
        v1 = __fadd_rn(v1, a.y);
        v2 = __fadd_rn(v2, bb.x);
        v3 = __fadd_rn(v3, bb.y);
        float s = 0.f;
        if (v0 >= THRESH) { v0 = __fadd_rn(v0, -THRESH); s += 0.25f; }
        if (v1 >= THRESH) { v1 = __fadd_rn(v1, -THRESH); s += 0.25f; }
        if (v2 >= THRESH) { v2 = __fadd_rn(v2, -THRESH); s += 0.25f; }
        if (v3 >= THRESH) { v3 = __fadd_rn(v3, -THRESH); s += 0.25f; }
        *q = s;
        p += stride;
        q += ostride;
    }
}

// ---------------- final linear: (BT,1024) @ (11,1024)^T ----------------
__global__ void linear_kernel(const float* __restrict__ in, const float* __restrict__ w,
                              float* __restrict__ out) {
    int n = blockIdx.x;
    __shared__ float srow[1024];
    for (int i = threadIdx.x; i < 1024; i += blockDim.x) srow[i] = in[(size_t)n * 1024 + i];
    __syncthreads();
    int cls = threadIdx.x;
    if (cls >= 11) return;
    const float* wr = w + (size_t)cls * 1024;
    float acc = 0.f;
    for (int i = 0; i < 1024; i++) acc = __fmaf_rn(srow[i], wr[i], acc);
    out[(size_t)n * 11 + cls] = acc;
}

extern "C" void kernel_launch(void* const* d_in, const int* in_sizes, int n_in,
                              void* d_out, int out_size) {
    const float* x   = (const float*)d_in[0];
    const float* c0v = (const float*)d_in[1];
    const float* c0g = (const float*)d_in[2];
    const float* c1v = (const float*)d_in[3];
    const float* c1g = (const float*)d_in[4];
    const float* c2v = (const float*)d_in[5];
    const float* c2g = (const float*)d_in[6];
    const float* c3v = (const float*)d_in[7];
    const float* c3g = (const float*)d_in[8];
    const float* lv  = (const float*)d_in[9];
    const float* lg  = (const float*)d_in[10];

    float *bufA, *bufB, *w0, *w1, *w2, *w3, *wl;
    cudaGetSymbolAddress((void**)&bufA, g_bufA);
    cudaGetSymbolAddress((void**)&bufB, g_bufB);
    cudaGetSymbolAddress((void**)&w0, g_w0);
    cudaGetSymbolAddress((void**)&w1, g_w1);
    cudaGetSymbolAddress((void**)&w2, g_w2);
    cudaGetSymbolAddress((void**)&w3, g_w3);
    cudaGetSymbolAddress((void**)&wl, g_wl);

    const int B = 32, T = 50, BT = B * T;

    // all weight norms in one launch
    wnorm_all<<<131, 64>>>(c0v, c0g, c1v, c1g, c2v, c2g, c3v, c3g, lv, lg,
                           w0, w1, w2, w3, wl);

    // smem for unfused convs
    const int smem1 = (1 * 8 * 34 * 34 + 9 * 8 * 16) * 4;      // 41600
    const int smem2 = (2 * 16 * 18 * 18 + 9 * 16 * 32) * 4;    // 59904
    const int smem3 = (2 * 32 * 10 * 10 + 9 * 32 * 64) * 4;    // 99328 -> opt-in

    cudaFuncSetAttribute(conv3x3_blk<8, 16, 32, 1>,
                         cudaFuncAttributeMaxDynamicSharedMemorySize, smem1);
    cudaFuncSetAttribute(conv3x3_blk<16, 32, 16, 2>,
                         cudaFuncAttributeMaxDynamicSharedMemorySize, smem2);
    cudaFuncSetAttribute(conv3x3_blk<32, 64, 8, 2>,
                         cudaFuncAttributeMaxDynamicSharedMemorySize, smem3);

    // layer 0 fused: conv(2->8,64x64) + IAF + pool -> bufB (B*T, 8, 32, 32)
    l0_fused<<<B * 8, 128>>>(x, w0, bufB);

    // layer 1: conv(8->16, 32x32) -> IAF+pool -> 16x16
    conv3x3_blk<8, 16, 32, 1><<<BT, 256, smem1>>>(bufB, w1, bufA);
    {
        int total = B * 16 * 16 * 16;
        iaf_pool_kernel<16, 32, 50><<<(total + 255) / 256, 256>>>(bufA, bufB, B);
    }
    // layer 2: conv(16->32, 16x16) -> IAF+pool -> 8x8
    conv3x3_blk<16, 32, 16, 2><<<BT / 2, 256, smem2>>>(bufB, w2, bufA);
    {
        int total = B * 32 * 8 * 8;
        iaf_pool_kernel<32, 16, 50><<<(total + 255) / 256, 256>>>(bufA, bufB, B);
    }
    // layer 3: conv(32->64, 8x8) -> IAF+pool -> 4x4
    conv3x3_blk<32, 64, 8, 2><<<BT / 2, 256, smem3>>>(bufB, w3, bufA);
    {
        int total = B * 64 * 4 * 4;
        iaf_pool_kernel<64, 8, 50><<<(total + 255) / 256, 256>>>(bufA, bufB, B);
    }
    // linear
    linear_kernel<<<BT, 32>>>(bufB, wl, (float*)d_out);
}

// round 6
// speedup vs baseline: 2.2632x; 1.0032x over previous
#include <cuda_runtime.h>
#include <math.h>

#define THRESH 0.1f

// ---------------- scratch (no allocations allowed) ----------------
__device__ float g_bufA[26214400];   // max: 1600*16*32*32 (100 MiB) — conv outputs (syn)
__device__ float g_bufB[13107200];   // max: 1600*8*32*32  ( 50 MiB) — pooled spikes
__device__ float g_w0[9 * 2 * 8];    // [k][ci][co] layout
__device__ float g_w1[9 * 8 * 16];
__device__ float g_w2[9 * 16 * 32];
__device__ float g_w3[9 * 32 * 64];
__device__ float g_wl[11 * 1024];

// ---------------- fused weight norm (all layers, one launch) ----------------
__global__ void wnorm_all(const float* __restrict__ c0v, const float* __restrict__ c0g,
                          const float* __restrict__ c1v, const float* __restrict__ c1g,
                          const float* __restrict__ c2v, const float* __restrict__ c2g,
                          const float* __restrict__ c3v, const float* __restrict__ c3g,
                          const float* __restrict__ lv,  const float* __restrict__ lg,
                          float* __restrict__ w0, float* __restrict__ w1,
                          float* __restrict__ w2, float* __restrict__ w3,
                          float* __restrict__ wl) {
    int r = blockIdx.x;
    const float* v = 0; const float* g = 0; float* w = 0;
    int CIN = 0, COUT = 0, co = 0;
    bool lin = false;
    if (r < 8)        { v = c0v; g = c0g; w = w0; CIN = 2;  COUT = 8;  co = r; }
    else if (r < 24)  { v = c1v; g = c1g; w = w1; CIN = 8;  COUT = 16; co = r - 8; }
    else if (r < 56)  { v = c2v; g = c2g; w = w2; CIN = 16; COUT = 32; co = r - 24; }
    else if (r < 120) { v = c3v; g = c3g; w = w3; CIN = 32; COUT = 64; co = r - 56; }
    else              { lin = true; co = r - 120; }

    __shared__ float snorm;
    if (!lin) {
        const float* vr = v + (size_t)co * CIN * 9;
        if (threadIdx.x == 0) {
            float s = 0.f;
            for (int i = 0; i < CIN * 9; i++) s = __fadd_rn(s, __fmul_rn(vr[i], vr[i]));
            snorm = sqrtf(s);
        }
        __syncthreads();
        float norm = snorm, gg = g[co];
        for (int idx = threadIdx.x; idx < CIN * 9; idx += blockDim.x) {
            int ci = idx / 9, k = idx % 9;
            w[((size_t)k * CIN + ci) * COUT + co] = __fdiv_rn(__fmul_rn(gg, vr[idx]), norm);
        }
    } else {
        const float* vr = lv + (size_t)co * 1024;
        if (threadIdx.x == 0) {
            float s = 0.f;
            for (int i = 0; i < 1024; i++) s = __fadd_rn(s, __fmul_rn(vr[i], vr[i]));
            snorm = sqrtf(s);
        }
        __syncthreads();
        float norm = snorm, gg = lg[co];
        for (int i = threadIdx.x; i < 1024; i += blockDim.x)
            wl[(size_t)co * 1024 + i] = __fdiv_rn(__fmul_rn(gg, vr[i]), norm);
    }
}

// ---------------- layer 0 fully fused: conv(2->8,64x64) + IAF(T=50) + 2x2 pool ----------------
// Block = (image b, 16x32 pre-pool spatial tile). 512 threads = 4 cout-groups x 128 pixel-threads.
// Each thread holds 2 couts x 4 membranes in registers across all T; syn never hits HBM.
__global__ void __launch_bounds__(512) l0_fused(const float* __restrict__ x,
                                                const float* __restrict__ wt,
                                                float* __restrict__ out) {
    const int PW = 36, CPH = 18 * 36;       // padded tile: 2 x 18 x 36 (cols 0..33 used)
    __shared__ float sw[144];               // [k][ci][co] = 9*2*8
    __shared__ float sin[2 * 18 * 36];

    const int b = blockIdx.x >> 3;
    const int tile = blockIdx.x & 7;
    const int ty0 = (tile >> 1) * 16;       // pre-pool row origin (0,16,32,48)
    const int tx0 = (tile & 1) * 32;        // pre-pool col origin (0,32)
    const int tid = threadIdx.x;
    if (tid < 144) sw[tid] = wt[tid];

    const int cg = tid >> 7;                // cout group: couts {2cg, 2cg+1}
    const int ptid = tid & 127;             // pixel thread within group
    const int py = ptid >> 4, px = ptid & 15;
    const int y0 = 2 * py, x0 = 2 * px;     // quad origin in padded-local coords
    const int co0 = cg * 2;

    float m[2][4];
#pragma unroll
    for (int c = 0; c < 2; c++) { m[c][0] = 0.f; m[c][1] = 0.f; m[c][2] = 0.f; m[c][3] = 0.f; }

    const int Y2 = (ty0 >> 1) + py, X2 = (tx0 >> 1) + px;

    for (int t = 0; t < 50; t++) {
        const float* xp = x + ((size_t)(b * 50 + t)) * 2 * 4096;
        // cooperative padded tile load (zero outside image)
        for (int i = tid; i < 2 * 18 * 34; i += 512) {
            int c = i / 612;
            int r = i - c * 612;
            int yy = r / 34, xx = r - yy * 34;
            int gy = ty0 + yy - 1, gx = tx0 + xx - 1;
            float v = 0.f;
            if (gy >= 0 && gy < 64 && gx >= 0 && gx < 64) v = xp[c * 4096 + gy * 64 + gx];
            sin[c * CPH + yy * PW + xx] = v;
        }
        __syncthreads();

        // preload 2ci x 4x4 input window into regs (aligned float2 loads)
        float inr[2][4][4];
#pragma unroll
        for (int ci = 0; ci < 2; ci++) {
#pragma unroll
            for (int r = 0; r < 4; r++) {
                const float* rp = sin + ci * CPH + (y0 + r) * PW + x0;
                float2 a = *reinterpret_cast<const float2*>(rp);
                float2 bb = *reinterpret_cast<const float2*>(rp + 2);
                inr[ci][r][0] = a.x; inr[ci][r][1] = a.y;
                inr[ci][r][2] = bb.x; inr[ci][r][3] = bb.y;
            }
        }
        __syncthreads();   // sin free for next t

        float acc[2][4];
#pragma unroll
        for (int c = 0; c < 2; c++) { acc[c][0] = 0.f; acc[c][1] = 0.f; acc[c][2] = 0.f; acc[c][3] = 0.f; }
#pragma unroll
        for (int ky = 0; ky < 3; ky++) {
#pragma unroll
            for (int kx = 0; kx < 3; kx++) {
#pragma unroll
                for (int ci = 0; ci < 2; ci++) {
                    float i00 = inr[ci][ky][kx];
                    float i01 = inr[ci][ky][kx + 1];
                    float i10 = inr[ci][ky + 1][kx];
                    float i11 = inr[ci][ky + 1][kx + 1];
                    const float2 wv = *reinterpret_cast<const float2*>(
                        sw + ((ky * 3 + kx) * 2 + ci) * 8 + co0);
                    acc[0][0] = __fmaf_rn(i00, wv.x, acc[0][0]);
                    acc[0][1] = __fmaf_rn(i01, wv.x, acc[0][1]);
                    acc[0][2] = __fmaf_rn(i10, wv.x, acc[0][2]);
                    acc[0][3] = __fmaf_rn(i11, wv.x, acc[0][3]);
                    acc[1][0] = __fmaf_rn(i00, wv.y, acc[1][0]);
                    acc[1][1] = __fmaf_rn(i01, wv.y, acc[1][1]);
                    acc[1][2] = __fmaf_rn(i10, wv.y, acc[1][2]);
                    acc[1][3] = __fmaf_rn(i11, wv.y, acc[1][3]);
                }
            }
        }

        // IAF membrane update + pool + store
        float* op = out + ((size_t)(b * 50 + t) * 8 + co0) * 1024 + Y2 * 32 + X2;
#pragma unroll
        for (int c = 0; c < 2; c++) {
            float s = 0.f;
            m[c][0] = __fadd_rn(m[c][0], acc[c][0]);
            m[c][1] = __fadd_rn(m[c][1], acc[c][1]);
            m[c][2] = __fadd_rn(m[c][2], acc[c][2]);
            m[c][3] = __fadd_rn(m[c][3], acc[c][3]);
            if (m[c][0] >= THRESH) { m[c][0] = __fadd_rn(m[c][0], -THRESH); s += 0.25f; }
            if (m[c][1] >= THRESH) { m[c][1] = __fadd_rn(m[c][1], -THRESH); s += 0.25f; }
            if (m[c][2] >= THRESH) { m[c][2] = __fadd_rn(m[c][2], -THRESH); s += 0.25f; }
            if (m[c][3] >= THRESH) { m[c][3] = __fadd_rn(m[c][3], -THRESH); s += 0.25f; }
            op[c * 1024] = s;
        }
    }
}

// ---------------- 3x3 SAME conv, register-blocked 2x2 x 8-channel ----------------
// Zero-padded smem tile; FMA chain per output exactly (ky,kx,ci), ci innermost.
template <int CIN, int COUT, int H, int IPB>
__global__ void conv3x3_blk(const float* __restrict__ in, const float* __restrict__ wt,
                            float* __restrict__ out) {
    const int W = H, HW = H * W, PW = W + 2, PHW = (H + 2) * PW;
    const int HW4 = HW / 4, W2 = W / 2, NCG = COUT / 8;
    extern __shared__ float smem[];
    float* sin = smem;                         // IPB*CIN*PHW (zero padded)
    float* sw = smem + IPB * CIN * PHW;        // 9*CIN*COUT

    const int n0 = blockIdx.x * IPB;
    for (int i = threadIdx.x; i < IPB * CIN * PHW; i += blockDim.x) sin[i] = 0.f;
    for (int i = threadIdx.x; i < 9 * CIN * COUT; i += blockDim.x) sw[i] = wt[i];
    __syncthreads();
    for (int i = threadIdx.x; i < IPB * CIN * HW; i += blockDim.x) {
        int img = i / (CIN * HW);
        int rem = i - img * (CIN * HW);
        int ci = rem / HW;
        int p = rem - ci * HW;
        int y = p / W;
        int x = p - y * W;
        sin[img * CIN * PHW + ci * PHW + (y + 1) * PW + (x + 1)] = in[(size_t)n0 * CIN * HW + i];
    }
    __syncthreads();

    const int ITEMS = IPB * HW4 * NCG;
    for (int item = threadIdx.x; item < ITEMS; item += blockDim.x) {
        int cg = item / (IPB * HW4);
        int rem = item - cg * (IPB * HW4);
        int img = rem / HW4;
        int q = rem - img * HW4;
        int y2 = q / W2, x2 = q - y2 * W2;
        int y0 = 2 * y2, x0 = 2 * x2;
        const float* simg = sin + img * CIN * PHW;

        float acc[8][4];
#pragma unroll
        for (int c = 0; c < 8; c++) {
            acc[c][0] = 0.f; acc[c][1] = 0.f; acc[c][2] = 0.f; acc[c][3] = 0.f;
        }
#pragma unroll
        for (int ky = 0; ky < 3; ky++) {
#pragma unroll
            for (int kx = 0; kx < 3; kx++) {
                const float* ip = simg + (y0 + ky) * PW + (x0 + kx);
                const float* wp = sw + (ky * 3 + kx) * CIN * COUT + cg * 8;
#pragma unroll 4
                for (int ci = 0; ci < CIN; ci++) {
                    float i00, i01, i10, i11;
                    if (kx != 1) {   // compile-time: even offset -> aligned float2
                        float2 a = *reinterpret_cast<const float2*>(ip + ci * PHW);
                        float2 bb = *reinterpret_cast<const float2*>(ip + ci * PHW + PW);
                        i00 = a.x; i01 = a.y; i10 = bb.x; i11 = bb.y;
                    } else {
                        i00 = ip[ci * PHW];
                        i01 = ip[ci * PHW + 1];
                        i10 = ip[ci * PHW + PW];
                        i11 = ip[ci * PHW + PW + 1];
                    }
                    const float4 wa = *reinterpret_cast<const float4*>(wp + ci * COUT);
                    const float4 wb = *reinterpret_cast<const float4*>(wp + ci * COUT + 4);
                    float wv[8] = {wa.x, wa.y, wa.z, wa.w, wb.x, wb.y, wb.z, wb.w};
#pragma unroll
                    for (int c = 0; c < 8; c++) {
                        acc[c][0] = __fmaf_rn(i00, wv[c], acc[c][0]);
                        acc[c][1] = __fmaf_rn(i01, wv[c], acc[c][1]);
                        acc[c][2] = __fmaf_rn(i10, wv[c], acc[c][2]);
                        acc[c][3] = __fmaf_rn(i11, wv[c], acc[c][3]);
                    }
                }
            }
        }
        float* op = out + ((size_t)(n0 + img) * COUT + cg * 8) * HW + y0 * W + x0;
#pragma unroll
        for (int c = 0; c < 8; c++) {
            float2 r0; r0.x = acc[c][0]; r0.y = acc[c][1];
            float2 r1; r1.x = acc[c][2]; r1.y = acc[c][3];
            *reinterpret_cast<float2*>(op + c * HW) = r0;
            *reinterpret_cast<float2*>(op + c * HW + W) = r1;
        }
    }
}

// ---------------- fused IAF (integrate-and-fire over T) + 2x2 avg pool ----------------
template <int C, int H, int T>
__global__ void iaf_pool_kernel(const float* __restrict__ syn, float* __restrict__ out, int B) {
    const int W = H, HW = H * W, H2 = H / 2, W2 = W / 2, HW2 = H2 * W2;
    int idx = blockIdx.x * blockDim.x + threadIdx.x;
    int total = B * C * HW2;
    if (idx >= total) return;
    int x2 = idx % W2;
    int r = idx / W2;
    int y2 = r % H2;
    r /= H2;
    int c = r % C;
    int b = r / C;

    const size_t stride = (size_t)C * HW;
    const size_t ostride = (size_t)C * HW2;
    const float* p = syn + ((size_t)b * T) * stride + (size_t)c * HW + (size_t)(2 * y2) * W + 2 * x2;
    float* q = out + ((size_t)b * T) * ostride + (size_t)c * HW2 + (size_t)y2 * W2 + x2;

    float v0 = 0.f, v1 = 0.f, v2 = 0.f, v3 = 0.f;
#pragma unroll 2
    for (int t = 0; t < T; t++) {
        const float2 a = *reinterpret_cast<const float2*>(p);
        const float2 bb = *reinterpret_cast<const float2*>(p + W);
        v0 = __fadd_rn(v0, a.x);
        v1 = __fadd_rn(v1, a.y);
        v2 = __fadd_rn(v2, bb.x);
        v3 = __fadd_rn(v3, bb.y);
        float s = 0.f;
        if (v0 >= THRESH) { v0 = __fadd_rn(v0, -THRESH); s += 0.25f; }
        if (v1 >= THRESH) { v1 = __fadd_rn(v1, -THRESH); s += 0.25f; }
        if (v2 >= THRESH) { v2 = __fadd_rn(v2, -THRESH); s += 0.25f; }
        if (v3 >= THRESH) { v3 = __fadd_rn(v3, -THRESH); s += 0.25f; }
        *q = s;
        p += stride;
        q += ostride;
    }
}

// ---------------- final linear: (BT,1024) @ (11,1024)^T ----------------
__global__ void linear_kernel(const float* __restrict__ in, const float* __restrict__ w,
                              float* __restrict__ out) {
    int n = blockIdx.x;
    __shared__ float srow[1024];
    for (int i = threadIdx.x; i < 1024; i += blockDim.x) srow[i] = in[(size_t)n * 1024 + i];
    __syncthreads();
    int cls = threadIdx.x;
    if (cls >= 11) return;
    const float* wr = w + (size_t)cls * 1024;
    float acc = 0.f;
    for (int i = 0; i < 1024; i++) acc = __fmaf_rn(srow[i], wr[i], acc);
    out[(size_t)n * 11 + cls] = acc;
}

extern "C" void kernel_launch(void* const* d_in, const int* in_sizes, int n_in,
                              void* d_out, int out_size) {
    const float* x   = (const float*)d_in[0];
    const float* c0v = (const float*)d_in[1];
    const float* c0g = (const float*)d_in[2];
    const float* c1v = (const float*)d_in[3];
    const float* c1g = (const float*)d_in[4];
    const float* c2v = (const float*)d_in[5];
    const float* c2g = (const float*)d_in[6];
    const float* c3v = (const float*)d_in[7];
    const float* c3g = (const float*)d_in[8];
    const float* lv  = (const float*)d_in[9];
    const float* lg  = (const float*)d_in[10];

    float *bufA, *bufB, *w0, *w1, *w2, *w3, *wl;
    cudaGetSymbolAddress((void**)&bufA, g_bufA);
    cudaGetSymbolAddress((void**)&bufB, g_bufB);
    cudaGetSymbolAddress((void**)&w0, g_w0);
    cudaGetSymbolAddress((void**)&w1, g_w1);
    cudaGetSymbolAddress((void**)&w2, g_w2);
    cudaGetSymbolAddress((void**)&w3, g_w3);
    cudaGetSymbolAddress((void**)&wl, g_wl);

    const int B = 32, T = 50, BT = B * T;

    // all weight norms in one launch
    wnorm_all<<<131, 64>>>(c0v, c0g, c1v, c1g, c2v, c2g, c3v, c3g, lv, lg,
                           w0, w1, w2, w3, wl);

    // smem for unfused convs
    const int smem1 = (1 * 8 * 34 * 34 + 9 * 8 * 16) * 4;      // 41600
    const int smem2 = (2 * 16 * 18 * 18 + 9 * 16 * 32) * 4;    // 59904
    const int smem3 = (2 * 32 * 10 * 10 + 9 * 32 * 64) * 4;    // 99328 -> opt-in

    cudaFuncSetAttribute(conv3x3_blk<8, 16, 32, 1>,
                         cudaFuncAttributeMaxDynamicSharedMemorySize, smem1);
    cudaFuncSetAttribute(conv3x3_blk<16, 32, 16, 2>,
                         cudaFuncAttributeMaxDynamicSharedMemorySize, smem2);
    cudaFuncSetAttribute(conv3x3_blk<32, 64, 8, 2>,
                         cudaFuncAttributeMaxDynamicSharedMemorySize, smem3);

    // layer 0 fused: conv(2->8,64x64) + IAF + pool -> bufB (B*T, 8, 32, 32)
    l0_fused<<<B * 8, 512>>>(x, w0, bufB);

    // layer 1: conv(8->16, 32x32) -> IAF+pool -> 16x16
    conv3x3_blk<8, 16, 32, 1><<<BT, 256, smem1>>>(bufB, w1, bufA);
    {
        int total = B * 16 * 16 * 16;
        iaf_pool_kernel<16, 32, 50><<<(total + 255) / 256, 256>>>(bufA, bufB, B);
    }
    // layer 2: conv(16->32, 16x16) -> IAF+pool -> 8x8
    conv3x3_blk<16, 32, 16, 2><<<BT / 2, 256, smem2>>>(bufB, w2, bufA);
    {
        int total = B * 32 * 8 * 8;
        iaf_pool_kernel<32, 16, 50><<<(total + 255) / 256, 256>>>(bufA, bufB, B);
    }
    // layer 3: conv(32->64, 8x8) -> IAF+pool -> 4x4
    conv3x3_blk<32, 64, 8, 2><<<BT / 2, 256, smem3>>>(bufB, w3, bufA);
    {
        int total = B * 64 * 4 * 4;
        iaf_pool_kernel<64, 8, 50><<<(total + 255) / 256, 256>>>(bufA, bufB, B);
    }
    // linear
    linear_kernel<<<BT, 32>>>(bufB, wl, (float*)d_out);
}